// round 9
// baseline (speedup 1.0000x reference)
#include <cuda_runtime.h>
#include <cstddef>

// Problem constants
constexpr int Bn = 8;
constexpr int S  = 160;
constexpr int D  = 256;
constexpr int RS = Bn * S;           // 1280 rows of x (flattened)
constexpr int P  = S * (S - 1) / 2;  // 12720 pairs

// K-split GEMM partials: g_p[ksplit][0]=x@Wi partial, g_p[ksplit][1]=x@Wj partial
constexpr int KS    = 2;
constexpr int KHALF = D / KS;        // 128
__device__ float g_p[KS][2][RS * D]; // 10.5 MB scratch

// ---------------------------------------------------------------------------
// Packed f32x2 helpers
// ---------------------------------------------------------------------------
__device__ __forceinline__ void ffma2(unsigned long long& d,
                                      unsigned long long a,
                                      unsigned long long b) {
    asm("fma.rn.f32x2 %0, %1, %2, %0;" : "+l"(d) : "l"(a), "l"(b));
}
__device__ __forceinline__ unsigned long long dup2(float x) {
    unsigned long long r;
    asm("mov.b64 %0, {%1, %1};" : "=l"(r) : "r"(__float_as_uint(x)));
    return r;
}
__device__ __forceinline__ unsigned long long add2(unsigned long long a,
                                                   unsigned long long b) {
    unsigned long long r;
    asm("add.rn.f32x2 %0, %1, %2;" : "=l"(r) : "l"(a), "l"(b));
    return r;
}
union F2U { unsigned long long u; float2 f; };
__device__ __forceinline__ float2 as_f2(unsigned long long v) { F2U t; t.u = v; return t.f; }

// ---------------------------------------------------------------------------
// Kernel 1: dual GEMM, M=1280, N=512 (Wi|Wj), K=256 with K-split 2.
// BM=64, BN=64, BK=16, 128 threads, micro-tile 4 rows x 8 cols:
// per k-step = 1 LDS.128 (a) + 2 LDS.128 (w) + 4 dup-MOV + 16 FFMA2
// -> FMA-pipe bound. Grid (20, 8, 2) = 320 blocks. No bias here (in expand).
// ---------------------------------------------------------------------------
constexpr int BM = 64, BN = 64, BK = 16;
constexpr int NTK = KHALF / BK;  // 8 k-tiles per block

__global__ __launch_bounds__(128) void gemm_kernel(
    const float* __restrict__ x,
    const float* __restrict__ W)
{
    __shared__ float xs[2][BK][BM + 4];               // transposed x tile (272B rows)
    __shared__ __align__(16) float ws[2][BK][BN + 4]; // W tile

    const int t  = threadIdx.x;
    const int r0 = blockIdx.x * BM;
    const int by = blockIdx.y;
    const int half = by >> 2;                 // 0 -> Wi, 1 -> Wj
    const int c0 = (by & 3) * BN;             // column within the half
    const int ks = blockIdx.z;
    const int k0 = ks * KHALF;
    const int wbase = half * D + k0;          // starting W row for this block

    const float4* x4 = reinterpret_cast<const float4*>(x);
    const float4* W4 = reinterpret_cast<const float4*>(W);

    // compute mapping: rows r0 + ty*4 .. +3 ; cols c0 + tx*8 .. +7
    const int ty = t >> 3;   // 0..15
    const int tx = t & 7;    // 0..7

    // staging mapping (idx = t + 128q over 256 float4s per tile)
    const int xrow = t >> 2, xch = t & 3;     // + 32q rows
    const int wrow = t >> 4, wch = t & 15;    // + 8q rows

    unsigned long long acc[4][4];
    #pragma unroll
    for (int r = 0; r < 4; r++)
        #pragma unroll
        for (int c = 0; c < 4; c++) acc[r][c] = 0ull;

    float4 xv[2], wv[2];

    // prefetch tile 0
    #pragma unroll
    for (int q = 0; q < 2; q++) {
        xv[q] = x4[(size_t)(r0 + xrow + 32 * q) * 64 + (k0 >> 2) + xch];
        wv[q] = W4[(size_t)(wbase + wrow + 8 * q) * 64 + (c0 >> 2) + wch];
    }
    #pragma unroll
    for (int q = 0; q < 2; q++) {
        const int rr = xrow + 32 * q;
        xs[0][xch * 4 + 0][rr] = xv[q].x;
        xs[0][xch * 4 + 1][rr] = xv[q].y;
        xs[0][xch * 4 + 2][rr] = xv[q].z;
        xs[0][xch * 4 + 3][rr] = xv[q].w;
        *reinterpret_cast<float4*>(&ws[0][wrow + 8 * q][wch * 4]) = wv[q];
    }
    __syncthreads();

    #pragma unroll 1
    for (int kt = 0; kt < NTK; kt++) {
        const int cur = kt & 1;
        const int nxt = cur ^ 1;

        if (kt + 1 < NTK) {  // global prefetch into registers
            #pragma unroll
            for (int q = 0; q < 2; q++) {
                xv[q] = x4[(size_t)(r0 + xrow + 32 * q) * 64 + (k0 >> 2) + (kt + 1) * 4 + xch];
                wv[q] = W4[(size_t)(wbase + (kt + 1) * BK + wrow + 8 * q) * 64 + (c0 >> 2) + wch];
            }
        }

        #pragma unroll
        for (int k = 0; k < BK; k++) {
            const float4 av = *reinterpret_cast<const float4*>(&xs[cur][k][ty * 4]);
            const ulonglong2 wq0 = *reinterpret_cast<const ulonglong2*>(&ws[cur][k][tx * 8]);
            const ulonglong2 wq1 = *reinterpret_cast<const ulonglong2*>(&ws[cur][k][tx * 8 + 4]);
            const unsigned long long a0 = dup2(av.x);
            const unsigned long long a1 = dup2(av.y);
            const unsigned long long a2 = dup2(av.z);
            const unsigned long long a3 = dup2(av.w);
            ffma2(acc[0][0], a0, wq0.x); ffma2(acc[0][1], a0, wq0.y);
            ffma2(acc[0][2], a0, wq1.x); ffma2(acc[0][3], a0, wq1.y);
            ffma2(acc[1][0], a1, wq0.x); ffma2(acc[1][1], a1, wq0.y);
            ffma2(acc[1][2], a1, wq1.x); ffma2(acc[1][3], a1, wq1.y);
            ffma2(acc[2][0], a2, wq0.x); ffma2(acc[2][1], a2, wq0.y);
            ffma2(acc[2][2], a2, wq1.x); ffma2(acc[2][3], a2, wq1.y);
            ffma2(acc[3][0], a3, wq0.x); ffma2(acc[3][1], a3, wq0.y);
            ffma2(acc[3][2], a3, wq1.x); ffma2(acc[3][3], a3, wq1.y);
        }

        if (kt + 1 < NTK) {
            #pragma unroll
            for (int q = 0; q < 2; q++) {
                const int rr = xrow + 32 * q;
                xs[nxt][xch * 4 + 0][rr] = xv[q].x;
                xs[nxt][xch * 4 + 1][rr] = xv[q].y;
                xs[nxt][xch * 4 + 2][rr] = xv[q].z;
                xs[nxt][xch * 4 + 3][rr] = xv[q].w;
                *reinterpret_cast<float4*>(&ws[nxt][wrow + 8 * q][wch * 4]) = wv[q];
            }
            __syncthreads();
        }
    }

    // epilogue: write partials (no bias)
    float* dst = g_p[ks][half];
    const int cc = c0 + tx * 8;
    #pragma unroll
    for (int r = 0; r < 4; r++) {
        const int row = r0 + ty * 4 + r;
        const float2 f0 = as_f2(acc[r][0]);
        const float2 f1 = as_f2(acc[r][1]);
        const float2 f2 = as_f2(acc[r][2]);
        const float2 f3 = as_f2(acc[r][3]);
        *reinterpret_cast<float4*>(&dst[(size_t)row * D + cc]) =
            make_float4(f0.x, f0.y, f1.x, f1.y);
        *reinterpret_cast<float4*>(&dst[(size_t)row * D + cc + 4]) =
            make_float4(f2.x, f2.y, f3.x, f3.y);
    }
}

// ---------------------------------------------------------------------------
// Kernel 2: pairwise expansion + K-split reduction + bias.
// Grid (55 triangle tiles, Bn, 2 D-halves), block 256 = 8 warps.
// Each warp owns TWO xa rows in registers (reduced + bias); xb staged in smem
// (reduced during staging). Per j-step: 1 LDS.128 -> up to 2 STG.128.
// ---------------------------------------------------------------------------
constexpr int TI  = 16;
constexpr int TPD = S / TI;                      // 10
constexpr int NTILES = TPD * (TPD + 1) / 2;      // 55

__global__ __launch_bounds__(256) void expand_kernel(
    float* __restrict__ out, const float* __restrict__ bias)
{
    __shared__ float4 sb[TI][32];

    // linear tile index -> (ti, tj) upper triangle incl. diagonal
    int rem = blockIdx.x, ti = 0;
    while (rem >= TPD - ti) { rem -= TPD - ti; ti++; }
    const int tj = ti + rem;

    const int b   = blockIdx.y;
    const int h   = blockIdx.z;   // D half
    const int i0  = ti * TI;
    const int j0  = tj * TI;
    const int tid = threadIdx.x;
    const int warp = tid >> 5;
    const int lane = tid & 31;

    const float4* pa0 = reinterpret_cast<const float4*>(g_p[0][0]);
    const float4* pa1 = reinterpret_cast<const float4*>(g_p[1][0]);
    const float4* pb0 = reinterpret_cast<const float4*>(g_p[0][1]);
    const float4* pb1 = reinterpret_cast<const float4*>(g_p[1][1]);

    // stage 16 xb half-rows, reducing the K-split partials
    #pragma unroll
    for (int q = 0; q < 2; q++) {
        const int k = tid + q * 256;
        const int r = k >> 5, c = k & 31;
        const size_t idx = (size_t)(b * S + j0 + r) * 64 + h * 32 + c;
        const float4 u = pb0[idx];
        const float4 v = pb1[idx];
        sb[r][c] = make_float4(u.x + v.x, u.y + v.y, u.z + v.z, u.w + v.w);
    }

    // this warp's two xa rows -> registers (reduced + bias)
    const float4 bv = reinterpret_cast<const float4*>(bias)[h * 32 + lane];
    const int ia = i0 + 2 * warp;
    const int ib = ia + 1;
    const size_t ixa = (size_t)(b * S + ia) * 64 + h * 32 + lane;
    const size_t ixb = (size_t)(b * S + ib) * 64 + h * 32 + lane;
    const float4 u0 = pa0[ixa], v0 = pa1[ixa];
    const float4 u1 = pa0[ixb], v1 = pa1[ixb];
    F2U a0lo, a0hi, a1lo, a1hi;
    a0lo.f = make_float2(u0.x + v0.x + bv.x, u0.y + v0.y + bv.y);
    a0hi.f = make_float2(u0.z + v0.z + bv.z, u0.w + v0.w + bv.w);
    a1lo.f = make_float2(u1.x + v1.x + bv.x, u1.y + v1.y + bv.y);
    a1hi.f = make_float2(u1.z + v1.z + bv.z, u1.w + v1.w + bv.w);

    __syncthreads();

    // p(i,j) = i*(2S-1-i)/2 + j - i - 1
    const int pb0i = ((2 * S - 1 - ia) * ia) / 2 + j0 - ia - 1;
    const int pb1i = ((2 * S - 1 - ib) * ib) / 2 + j0 - ib - 1;

    float4* out4 = reinterpret_cast<float4*>(out);
    float4* o0 = out4 + ((size_t)b * P + pb0i) * 64 + h * 32 + lane;
    float4* o1 = out4 + ((size_t)b * P + pb1i) * 64 + h * 32 + lane;

    #pragma unroll
    for (int jj = 0; jj < TI; jj++) {
        const float4 v = sb[jj][lane];
        F2U vlo, vhi;
        vlo.f = make_float2(v.x, v.y);
        vhi.f = make_float2(v.z, v.w);
        const int j = j0 + jj;

        if (j > ia) {
            F2U rlo, rhi;
            rlo.u = add2(a0lo.u, vlo.u);
            rhi.u = add2(a0hi.u, vhi.u);
            o0[(size_t)jj * 64] = make_float4(rlo.f.x, rlo.f.y, rhi.f.x, rhi.f.y);
        }
        if (j > ib) {
            F2U rlo, rhi;
            rlo.u = add2(a1lo.u, vlo.u);
            rhi.u = add2(a1hi.u, vhi.u);
            o1[(size_t)jj * 64] = make_float4(rlo.f.x, rlo.f.y, rhi.f.x, rhi.f.y);
        }
    }
}

// ---------------------------------------------------------------------------
extern "C" void kernel_launch(void* const* d_in, const int* in_sizes, int n_in,
                              void* d_out, int out_size)
{
    const float* x    = (const float*)d_in[0];   // (8,160,256) f32
    const float* W    = (const float*)d_in[1];   // (512,256)   f32
    const float* bias = (const float*)d_in[2];   // (256,)      f32
    float* out = (float*)d_out;                  // (8,12720,256) f32

    gemm_kernel<<<dim3(RS / BM, 2 * D / BN, KS), 128>>>(x, W);
    expand_kernel<<<dim3(NTILES, Bn, 2), 256>>>(out, bias);
}

// round 10
// speedup vs baseline: 1.5779x; 1.5779x over previous
#include <cuda_runtime.h>
#include <cstddef>

// Problem constants
constexpr int Bn = 8;
constexpr int S  = 160;
constexpr int D  = 256;
constexpr int RS = Bn * S;           // 1280 rows of x (flattened)
constexpr int P  = S * (S - 1) / 2;  // 12720 pairs

// Scratch (allocation-free __device__ globals)
__device__ float g_xa[RS * D];   // x@Wi + bias
__device__ float g_xb[RS * D];   // x@Wj

// ---------------------------------------------------------------------------
// Packed f32x2 helpers
// ---------------------------------------------------------------------------
__device__ __forceinline__ void ffma2(unsigned long long& d,
                                      unsigned long long a,
                                      unsigned long long b) {
    asm("fma.rn.f32x2 %0, %1, %2, %0;" : "+l"(d) : "l"(a), "l"(b));
}
__device__ __forceinline__ unsigned long long dup2(float x) {
    unsigned long long r;
    asm("mov.b64 %0, {%1, %1};" : "=l"(r) : "r"(__float_as_uint(x)));
    return r;
}
__device__ __forceinline__ unsigned long long add2(unsigned long long a,
                                                   unsigned long long b) {
    unsigned long long r;
    asm("add.rn.f32x2 %0, %1, %2;" : "=l"(r) : "l"(a), "l"(b));
    return r;
}
union F2U { unsigned long long u; float2 f; };
__device__ __forceinline__ float2 as_f2(unsigned long long v) { F2U t; t.u = v; return t.f; }

// ---------------------------------------------------------------------------
// Kernel 1: dual GEMM, M=1280, N=512 (Wi|Wj), K=256.
// BM=32, BN=32, BK=32, 128 threads, micro-tile 2 rows x 4 cols.
// Grid (40, 16) = 640 blocks -> ~4.3 blocks/SM: occupancy-based latency hiding.
// Per k-step: 1 LDS.64 (a, 4-way broadcast) + 1 LDS.128 (w, conflict-free)
//           + 2 dup-MOV + 4 FFMA2  -> FMA-pipe dominant.
// Double-buffered smem with register prefetch. Bias folded in epilogue.
// ---------------------------------------------------------------------------
constexpr int BM = 32, BN = 32, BK = 32;
constexpr int NT = D / BK;  // 8 k-tiles

__global__ __launch_bounds__(128) void gemm_kernel(
    const float* __restrict__ x,
    const float* __restrict__ W,
    const float* __restrict__ bias)
{
    __shared__ float xs[2][BK][BM + 2];               // transposed x tile
    __shared__ __align__(16) float ws[2][BK][BN + 4]; // W tile (36-float rows, 16B-aligned)

    const int t  = threadIdx.x;
    const int r0 = blockIdx.x * BM;
    const int by = blockIdx.y;
    const int half = by >> 3;                 // 0 -> Wi/g_xa, 1 -> Wj/g_xb
    const int c0 = (by & 7) * BN;             // column within the half
    const int wbase = half * D;               // W row base

    const float4* x4 = reinterpret_cast<const float4*>(x);
    const float4* W4 = reinterpret_cast<const float4*>(W);

    // compute mapping: rows 2*ty, 2*ty+1 ; cols 4*tx .. 4*tx+3
    const int ty = t >> 3;   // 0..15
    const int tx = t & 7;    // 0..7

    // staging mapping: 256 float4 per tile for each of x and W -> 2 per thread
    const int row0 = t >> 3, ch0 = t & 7;           // idx t
    const int row1 = (t + 128) >> 3, ch1 = t & 7;   // idx t+128

    unsigned long long acc[2][2];
    acc[0][0] = acc[0][1] = acc[1][0] = acc[1][1] = 0ull;

    float4 xv0, xv1, wv0, wv1;

    // prefetch tile 0
    xv0 = x4[(size_t)(r0 + row0) * 64 + ch0];
    xv1 = x4[(size_t)(r0 + row1) * 64 + ch1];
    wv0 = W4[(size_t)(wbase + row0) * 64 + (c0 >> 2) + ch0];
    wv1 = W4[(size_t)(wbase + row1) * 64 + (c0 >> 2) + ch1];

    // store tile 0
    xs[0][ch0 * 4 + 0][row0] = xv0.x;
    xs[0][ch0 * 4 + 1][row0] = xv0.y;
    xs[0][ch0 * 4 + 2][row0] = xv0.z;
    xs[0][ch0 * 4 + 3][row0] = xv0.w;
    xs[0][ch1 * 4 + 0][row1] = xv1.x;
    xs[0][ch1 * 4 + 1][row1] = xv1.y;
    xs[0][ch1 * 4 + 2][row1] = xv1.z;
    xs[0][ch1 * 4 + 3][row1] = xv1.w;
    *reinterpret_cast<float4*>(&ws[0][row0][ch0 * 4]) = wv0;
    *reinterpret_cast<float4*>(&ws[0][row1][ch1 * 4]) = wv1;
    __syncthreads();

    #pragma unroll 1
    for (int kt = 0; kt < NT; kt++) {
        const int cur = kt & 1;
        const int nxt = cur ^ 1;

        if (kt + 1 < NT) {  // global prefetch into registers
            const int kc = (kt + 1) * (BK / 4);
            xv0 = x4[(size_t)(r0 + row0) * 64 + kc + ch0];
            xv1 = x4[(size_t)(r0 + row1) * 64 + kc + ch1];
            wv0 = W4[(size_t)(wbase + (kt + 1) * BK + row0) * 64 + (c0 >> 2) + ch0];
            wv1 = W4[(size_t)(wbase + (kt + 1) * BK + row1) * 64 + (c0 >> 2) + ch1];
        }

        #pragma unroll
        for (int k = 0; k < BK; k++) {
            const float2 a2 = *reinterpret_cast<const float2*>(&xs[cur][k][2 * ty]);
            const ulonglong2 wq = *reinterpret_cast<const ulonglong2*>(&ws[cur][k][4 * tx]);
            const unsigned long long a0 = dup2(a2.x);
            const unsigned long long a1 = dup2(a2.y);
            ffma2(acc[0][0], a0, wq.x); ffma2(acc[0][1], a0, wq.y);
            ffma2(acc[1][0], a1, wq.x); ffma2(acc[1][1], a1, wq.y);
        }

        if (kt + 1 < NT) {
            xs[nxt][ch0 * 4 + 0][row0] = xv0.x;
            xs[nxt][ch0 * 4 + 1][row0] = xv0.y;
            xs[nxt][ch0 * 4 + 2][row0] = xv0.z;
            xs[nxt][ch0 * 4 + 3][row0] = xv0.w;
            xs[nxt][ch1 * 4 + 0][row1] = xv1.x;
            xs[nxt][ch1 * 4 + 1][row1] = xv1.y;
            xs[nxt][ch1 * 4 + 2][row1] = xv1.z;
            xs[nxt][ch1 * 4 + 3][row1] = xv1.w;
            *reinterpret_cast<float4*>(&ws[nxt][row0][ch0 * 4]) = wv0;
            *reinterpret_cast<float4*>(&ws[nxt][row1][ch1 * 4]) = wv1;
            __syncthreads();
        }
    }

    // epilogue: bias on Wi half, one STG.128 per row
    const int cc = c0 + 4 * tx;
    float4 bvec = make_float4(0.f, 0.f, 0.f, 0.f);
    if (!half) bvec = *reinterpret_cast<const float4*>(&bias[cc]);
    float* dst = half ? g_xb : g_xa;
    #pragma unroll
    for (int r = 0; r < 2; r++) {
        const int row = r0 + 2 * ty + r;
        const float2 f0 = as_f2(acc[r][0]);
        const float2 f1 = as_f2(acc[r][1]);
        *reinterpret_cast<float4*>(&dst[(size_t)row * D + cc]) =
            make_float4(f0.x + bvec.x, f0.y + bvec.y, f1.x + bvec.z, f1.y + bvec.w);
    }
}

// ---------------------------------------------------------------------------
// Kernel 2: pairwise expansion (R5 structure, measured 18.4us).
// Grid (55 triangle tiles, Bn, 2 D-halves), block 256 = 8 warps.
// Each warp owns TWO xa rows in registers; xb staged in smem.
// Per j-step: 1 LDS.128 -> up to 2 STG.128, packed f32x2 adds.
// ---------------------------------------------------------------------------
constexpr int TI  = 16;
constexpr int TPD = S / TI;                      // 10
constexpr int NTILES = TPD * (TPD + 1) / 2;      // 55

__global__ __launch_bounds__(256) void expand_kernel(float* __restrict__ out)
{
    __shared__ float4 sb[TI][32];

    // linear tile index -> (ti, tj) upper triangle incl. diagonal
    int rem = blockIdx.x, ti = 0;
    while (rem >= TPD - ti) { rem -= TPD - ti; ti++; }
    const int tj = ti + rem;

    const int b   = blockIdx.y;
    const int h   = blockIdx.z;   // D half
    const int i0  = ti * TI;
    const int j0  = tj * TI;
    const int tid = threadIdx.x;
    const int warp = tid >> 5;
    const int lane = tid & 31;

    const float4* xa4 = reinterpret_cast<const float4*>(g_xa);
    const float4* xb4 = reinterpret_cast<const float4*>(g_xb);

    // stage 16 xb half-rows
    #pragma unroll
    for (int q = 0; q < 2; q++) {
        const int k = tid + q * 256;
        const int r = k >> 5, c = k & 31;
        sb[r][c] = xb4[(size_t)(b * S + j0 + r) * 64 + h * 32 + c];
    }

    // this warp's two xa rows -> registers
    const int ia = i0 + 2 * warp;
    const int ib = ia + 1;
    const float4 A0 = xa4[(size_t)(b * S + ia) * 64 + h * 32 + lane];
    const float4 A1 = xa4[(size_t)(b * S + ib) * 64 + h * 32 + lane];
    F2U a0lo, a0hi, a1lo, a1hi;
    a0lo.f = make_float2(A0.x, A0.y); a0hi.f = make_float2(A0.z, A0.w);
    a1lo.f = make_float2(A1.x, A1.y); a1hi.f = make_float2(A1.z, A1.w);

    __syncthreads();

    // p(i,j) = i*(2S-1-i)/2 + j - i - 1
    const int p0 = ((2 * S - 1 - ia) * ia) / 2 + j0 - ia - 1;
    const int p1 = ((2 * S - 1 - ib) * ib) / 2 + j0 - ib - 1;

    float4* out4 = reinterpret_cast<float4*>(out);
    float4* o0 = out4 + ((size_t)b * P + p0) * 64 + h * 32 + lane;
    float4* o1 = out4 + ((size_t)b * P + p1) * 64 + h * 32 + lane;

    #pragma unroll
    for (int jj = 0; jj < TI; jj++) {
        const float4 v = sb[jj][lane];
        F2U vlo, vhi;
        vlo.f = make_float2(v.x, v.y);
        vhi.f = make_float2(v.z, v.w);
        const int j = j0 + jj;

        if (j > ia) {
            F2U rlo, rhi;
            rlo.u = add2(a0lo.u, vlo.u);
            rhi.u = add2(a0hi.u, vhi.u);
            o0[(size_t)jj * 64] = make_float4(rlo.f.x, rlo.f.y, rhi.f.x, rhi.f.y);
        }
        if (j > ib) {
            F2U rlo, rhi;
            rlo.u = add2(a1lo.u, vlo.u);
            rhi.u = add2(a1hi.u, vhi.u);
            o1[(size_t)jj * 64] = make_float4(rlo.f.x, rlo.f.y, rhi.f.x, rhi.f.y);
        }
    }
}

// ---------------------------------------------------------------------------
extern "C" void kernel_launch(void* const* d_in, const int* in_sizes, int n_in,
                              void* d_out, int out_size)
{
    const float* x    = (const float*)d_in[0];   // (8,160,256) f32
    const float* W    = (const float*)d_in[1];   // (512,256)   f32
    const float* bias = (const float*)d_in[2];   // (256,)      f32
    float* out = (float*)d_out;                  // (8,12720,256) f32

    gemm_kernel<<<dim3(RS / BM, 2 * D / BN), 128>>>(x, W, bias);
    expand_kernel<<<dim3(NTILES, Bn, 2), 256>>>(out);
}